// round 9
// baseline (speedup 1.0000x reference)
#include <cuda_runtime.h>
#include <cuda_bf16.h>
#include <cstdint>

// PostProcessor3D: threshold(0.9) -> 5x5x5 maxpool(stride1,pad2) -> strict peak mask.
// In: [64,512,512] f32.  Out: [64,512,512] f32.
//
// Block (128,4)=512 threads, full W=512 (float4/thread) x 4 H rows, marching
// 36 planes of a 32-deep D chunk in PAIRS. Grid 128x2 = 256 blocks, 2 blocks
// co-resident per SM (launch_bounds(512,2), 98KB smem/block).
//
// Raw-domain max (thr commutes with max; pads are 0). Threshold at emission:
//   out(od) = (cen==M3d && cen>THRESH) ? cen : 0.
//
// cp.async 6-buffer ring, 2 planes per iter, lookahead 4 planes, issue AFTER
// the barrier. Per iter k (planes p=2k, p+1):
//   wait_group 2  -> planes p, p+1 complete (p+2..p+3 may pend)
//   BAR           -> all threads' copies of p, p+1 visible; frees bufs (p-2),(p-1)
//   issue p+4 -> buf (p+4)%6=(p-2)%6, p+5 -> (p-1)%6   [readers were pre-BAR]
//   compute p, p+1
// Prologue issues planes 0..3. Off-range planes commit EMPTY groups.

#define Wd 512
#define Hd 512
#define Dd 64
#define TH 4
#define LR 8
#define DCH 32
#define NP (DCH + 4)        // 36 (even)
#define PSZ (Hd * Wd)
#define THRESH 0.9f
#define BUFSZ (LR * Wd)     // floats per buffer (4096)
#define NBUF 6

__device__ __forceinline__ void cp_async16(uint32_t dst, const void* src, int src_bytes) {
    asm volatile("cp.async.cg.shared.global [%0], [%1], 16, %2;\n"
                 :: "r"(dst), "l"(src), "r"(src_bytes));
}
__device__ __forceinline__ void cp_commit() {
    asm volatile("cp.async.commit_group;\n");
}
__device__ __forceinline__ void cp_wait2() {
    asm volatile("cp.async.wait_group 2;\n");
}
__device__ __forceinline__ void cp_wait0() {
    asm volatile("cp.async.wait_group 0;\n");
}

__device__ __forceinline__ float4 fmax4(float4 a, float4 b) {
    return make_float4(fmaxf(a.x, b.x), fmaxf(a.y, b.y),
                       fmaxf(a.z, b.z), fmaxf(a.w, b.w));
}

extern __shared__ float vsm[];   // [NBUF][LR][512] raw planes

__global__ __launch_bounds__(512, 2)
void peak3d_kernel(const float* __restrict__ in, float* __restrict__ out) {
    const int tx   = threadIdx.x;          // 0..127
    const int ty   = threadIdx.y;          // 0..3
    const int lane = tx & 31;
    const int c    = tx << 2;
    const int h0   = blockIdx.x * TH;
    const int d0   = blockIdx.y * DCH;

    const bool edgeL    = (lane == 0);
    const bool edgeR    = (lane == 31);
    const bool haveEdge = (edgeL && tx != 0) || (edgeR && tx != 127);
    const int  ec       = edgeL ? (c - 2) : (c + 4);

    // this thread copies loaded-rows ty and ty+4 of the strip [h0-2, h0+5]
    const int  k2  = ty + 4;
    const int  gh1 = h0 - 2 + ty;
    const int  gh2 = h0 + 2 + ty;
    const bool ok1 = ((unsigned)gh1 < (unsigned)Hd);
    const bool ok2 = (gh2 < Hd);

    const float* g1 = in + (size_t)(ok1 ? gh1 : 0) * Wd + c;
    const float* g2 = in + (size_t)(ok2 ? gh2 : 0) * Wd + c;

    const uint32_t sbase = (uint32_t)__cvta_generic_to_shared(vsm);
    const uint32_t dst1  = sbase + (uint32_t)(ty * Wd + c) * 4u;
    const uint32_t dst2  = sbase + (uint32_t)(k2 * Wd + c) * 4u;
    const uint32_t BUFB  = BUFSZ * 4u;

    // issue async copies for plane index pf (dl = d0-2+pf) into buf pf%NBUF.
    // pf >= NP: commit an EMPTY group (keeps wait counts aligned, no writes).
    auto issue = [&](int pf) {
        if (pf < NP) {
            int  dl  = d0 - 2 + pf;
            bool dok = ((unsigned)dl < (unsigned)Dd);
            int  dlc = dok ? dl : 0;
            uint32_t boff = (uint32_t)(pf % NBUF) * BUFB;
            cp_async16(dst1 + boff, g1 + (size_t)dlc * PSZ, (ok1 && dok) ? 16 : 0);
            cp_async16(dst2 + boff, g2 + (size_t)dlc * PSZ, (ok2 && dok) ? 16 : 0);
        }
        cp_commit();
    };

    // prologue: 4 planes in flight
    issue(0);
    issue(1);
    issue(2);
    issue(3);

    // rings (raw domain)
    float4 rp1 = make_float4(0.f, 0.f, 0.f, 0.f);
    float4 rp2 = rp1, rp3 = rp1, rp4 = rp1;          // m2d(p-1..p-4)
    float4 cen1 = rp1, cen2 = rp1;                   // cen(p-1), cen(p-2)

    float* outp = out + (size_t)d0 * PSZ + (size_t)(h0 + ty) * Wd + c;

    // compute one plane from buffer vb; ring update + optional emit
    auto plane = [&](const float* vb, bool emit) {
        const float* vr = vb + ty * Wd + c;
        float4 t0 = *(const float4*)(vr);
        float4 t1 = *(const float4*)(vr + 512);
        float4 t2 = *(const float4*)(vr + 1024);   // center row
        float4 t3 = *(const float4*)(vr + 1536);
        float4 t4 = *(const float4*)(vr + 2048);
        float4 cen = t2;
        float4 hm  = fmax4(fmax4(fmax4(t0, t1), fmax4(t2, t3)), t4);

        float2 eh = make_float2(0.f, 0.f);
        if (haveEdge) {
            const float* ep = vb + ty * Wd + ec;
            float2 e0 = *(const float2*)(ep);
            float2 e1 = *(const float2*)(ep + 512);
            float2 e2 = *(const float2*)(ep + 1024);
            float2 e3 = *(const float2*)(ep + 1536);
            float2 e4 = *(const float2*)(ep + 2048);
            eh.x = fmaxf(fmaxf(fmaxf(e0.x, e1.x), fmaxf(e2.x, e3.x)), e4.x);
            eh.y = fmaxf(fmaxf(fmaxf(e0.y, e1.y), fmaxf(e2.y, e3.y)), e4.y);
        }

        float l2 = __shfl_up_sync(0xffffffffu, hm.z, 1);
        float l1 = __shfl_up_sync(0xffffffffu, hm.w, 1);
        float r4 = __shfl_down_sync(0xffffffffu, hm.x, 1);
        float r5 = __shfl_down_sync(0xffffffffu, hm.y, 1);
        if (edgeL) { l2 = eh.x; l1 = eh.y; }
        if (edgeR) { r4 = eh.x; r5 = eh.y; }

        float m01 = fmaxf(hm.x, hm.y);
        float m12 = fmaxf(hm.y, hm.z);
        float m23 = fmaxf(hm.z, hm.w);
        float4 m;                               // m2d(p), raw
        m.x = fmaxf(fmaxf(l2, l1), fmaxf(m01, hm.z));
        m.y = fmaxf(l1, fmaxf(m01, m23));
        m.z = fmaxf(fmaxf(m01, m23), r4);
        m.w = fmaxf(fmaxf(m12, hm.w), fmaxf(r4, r5));

        if (emit) {
            float4 M3 = fmax4(fmax4(fmax4(rp4, rp3), fmax4(rp2, rp1)), m);
            float4 o;
            o.x = (cen2.x == M3.x && cen2.x > THRESH) ? cen2.x : 0.f;
            o.y = (cen2.y == M3.y && cen2.y > THRESH) ? cen2.y : 0.f;
            o.z = (cen2.z == M3.z && cen2.z > THRESH) ? cen2.z : 0.f;
            o.w = (cen2.w == M3.w && cen2.w > THRESH) ? cen2.w : 0.f;
            *(float4*)outp = o;
            outp += PSZ;
        }

        rp4 = rp3; rp3 = rp2; rp2 = rp1; rp1 = m;
        cen2 = cen1; cen1 = cen;
    };

    #pragma unroll 3
    for (int k = 0; k < NP / 2; ++k) {
        const int p = 2 * k;

        cp_wait2();         // planes p, p+1 complete (p+2, p+3 may pend)
        __syncthreads();    // copies of p, p+1 visible; bufs (p-2),(p-1) freed

        issue(p + 4);       // -> buf (p-2)%6, readers were pre-barrier
        issue(p + 5);       // -> buf (p-1)%6

        plane(vsm + (p % NBUF) * BUFSZ,       p     >= 4);
        plane(vsm + ((p + 1) % NBUF) * BUFSZ, p + 1 >= 4);
    }

    cp_wait0();   // drain trailing groups before exit
}

extern "C" void kernel_launch(void* const* d_in, const int* in_sizes, int n_in,
                              void* d_out, int out_size) {
    (void)in_sizes; (void)n_in; (void)out_size;
    const float* in = (const float*)d_in[0];
    float* out = (float*)d_out;

    const int smem_bytes = NBUF * BUFSZ * (int)sizeof(float);   // 98304
    cudaFuncSetAttribute(peak3d_kernel,
                         cudaFuncAttributeMaxDynamicSharedMemorySize, smem_bytes);

    dim3 block(128, 4);                 // 512 threads
    dim3 grid(Hd / TH, Dd / DCH);       // 128 x 2 = 256 blocks (2/SM resident)
    peak3d_kernel<<<grid, block, smem_bytes>>>(in, out);
}

// round 10
// speedup vs baseline: 1.0696x; 1.0696x over previous
#include <cuda_runtime.h>
#include <cuda_bf16.h>
#include <cstdint>

// PostProcessor3D: threshold(0.9) -> 5x5x5 maxpool(stride1,pad2) -> strict peak mask.
// In: [64,512,512] f32.  Out: [64,512,512] f32.
//
// Block (128,4)=512 threads, full W=512 (float4/thread) x 4 H rows, marching
// 36 planes of a 32-deep D chunk in TRIPLES. Grid 128x2 = 256 blocks, 2 blocks
// co-resident per SM (launch_bounds(512,2), 98KB smem/block).
//
// Raw-domain max (thr commutes with max; pads are 0). Threshold at emission:
//   out(od) = (cen==M3d && cen>THRESH) ? cen : 0.
//
// cp.async 6-buffer ring, 3 planes per iter, ONE barrier per 3 planes.
// Per iter k (planes p=3k..p+2):
//   issue p+3, p+4, p+5 (3 commits)     [targets bufs (p-3..p-1)%6, readers pre-BAR k]
//   wait_group 3 -> planes p..p+2 complete
//   BAR          -> all threads' copies of p..p+2 visible
//   compute p, p+1, p+2 (3 independent chains -> ILP)
// Prologue issues planes 0..2. Off-range planes commit EMPTY groups.

#define Wd 512
#define Hd 512
#define Dd 64
#define TH 4
#define LR 8
#define DCH 32
#define NP (DCH + 4)        // 36 = 12 * 3
#define PSZ (Hd * Wd)
#define THRESH 0.9f
#define BUFSZ (LR * Wd)     // floats per buffer (4096)
#define NBUF 6

__device__ __forceinline__ void cp_async16(uint32_t dst, const void* src, int src_bytes) {
    asm volatile("cp.async.cg.shared.global [%0], [%1], 16, %2;\n"
                 :: "r"(dst), "l"(src), "r"(src_bytes));
}
__device__ __forceinline__ void cp_commit() {
    asm volatile("cp.async.commit_group;\n");
}
__device__ __forceinline__ void cp_wait3() {
    asm volatile("cp.async.wait_group 3;\n");
}
__device__ __forceinline__ void cp_wait0() {
    asm volatile("cp.async.wait_group 0;\n");
}

__device__ __forceinline__ float4 fmax4(float4 a, float4 b) {
    return make_float4(fmaxf(a.x, b.x), fmaxf(a.y, b.y),
                       fmaxf(a.z, b.z), fmaxf(a.w, b.w));
}

extern __shared__ float vsm[];   // [NBUF][LR][512] raw planes

__global__ __launch_bounds__(512, 2)
void peak3d_kernel(const float* __restrict__ in, float* __restrict__ out) {
    const int tx   = threadIdx.x;          // 0..127
    const int ty   = threadIdx.y;          // 0..3
    const int lane = tx & 31;
    const int c    = tx << 2;
    const int h0   = blockIdx.x * TH;
    const int d0   = blockIdx.y * DCH;

    const bool edgeL    = (lane == 0);
    const bool edgeR    = (lane == 31);
    const bool haveEdge = (edgeL && tx != 0) || (edgeR && tx != 127);
    const int  ec       = edgeL ? (c - 2) : (c + 4);

    // this thread copies loaded-rows ty and ty+4 of the strip [h0-2, h0+5]
    const int  k2  = ty + 4;
    const int  gh1 = h0 - 2 + ty;
    const int  gh2 = h0 + 2 + ty;
    const bool ok1 = ((unsigned)gh1 < (unsigned)Hd);
    const bool ok2 = (gh2 < Hd);

    const float* g1 = in + (size_t)(ok1 ? gh1 : 0) * Wd + c;
    const float* g2 = in + (size_t)(ok2 ? gh2 : 0) * Wd + c;

    const uint32_t sbase = (uint32_t)__cvta_generic_to_shared(vsm);
    const uint32_t dst1  = sbase + (uint32_t)(ty * Wd + c) * 4u;
    const uint32_t dst2  = sbase + (uint32_t)(k2 * Wd + c) * 4u;
    const uint32_t BUFB  = BUFSZ * 4u;

    // issue async copies for plane index pf (dl = d0-2+pf) into buf pf%NBUF.
    // pf >= NP: commit an EMPTY group (keeps wait counts aligned, no writes).
    auto issue = [&](int pf) {
        if (pf < NP) {
            int  dl  = d0 - 2 + pf;
            bool dok = ((unsigned)dl < (unsigned)Dd);
            int  dlc = dok ? dl : 0;
            uint32_t boff = (uint32_t)(pf % NBUF) * BUFB;
            cp_async16(dst1 + boff, g1 + (size_t)dlc * PSZ, (ok1 && dok) ? 16 : 0);
            cp_async16(dst2 + boff, g2 + (size_t)dlc * PSZ, (ok2 && dok) ? 16 : 0);
        }
        cp_commit();
    };

    // prologue: 3 planes in flight
    issue(0);
    issue(1);
    issue(2);

    // rings (raw domain)
    float4 rp1 = make_float4(0.f, 0.f, 0.f, 0.f);
    float4 rp2 = rp1, rp3 = rp1, rp4 = rp1;          // m2d(p-1..p-4)
    float4 cen1 = rp1, cen2 = rp1;                   // cen(p-1), cen(p-2)

    float* outp = out + (size_t)d0 * PSZ + (size_t)(h0 + ty) * Wd + c;

    // compute one plane from buffer vb; ring update + optional emit
    auto plane = [&](const float* vb, bool emit) {
        const float* vr = vb + ty * Wd + c;
        float4 t0 = *(const float4*)(vr);
        float4 t1 = *(const float4*)(vr + 512);
        float4 t2 = *(const float4*)(vr + 1024);   // center row
        float4 t3 = *(const float4*)(vr + 1536);
        float4 t4 = *(const float4*)(vr + 2048);
        float4 cen = t2;
        float4 hm  = fmax4(fmax4(fmax4(t0, t1), fmax4(t2, t3)), t4);

        float2 eh = make_float2(0.f, 0.f);
        if (haveEdge) {
            const float* ep = vb + ty * Wd + ec;
            float2 e0 = *(const float2*)(ep);
            float2 e1 = *(const float2*)(ep + 512);
            float2 e2 = *(const float2*)(ep + 1024);
            float2 e3 = *(const float2*)(ep + 1536);
            float2 e4 = *(const float2*)(ep + 2048);
            eh.x = fmaxf(fmaxf(fmaxf(e0.x, e1.x), fmaxf(e2.x, e3.x)), e4.x);
            eh.y = fmaxf(fmaxf(fmaxf(e0.y, e1.y), fmaxf(e2.y, e3.y)), e4.y);
        }

        float l2 = __shfl_up_sync(0xffffffffu, hm.z, 1);
        float l1 = __shfl_up_sync(0xffffffffu, hm.w, 1);
        float r4 = __shfl_down_sync(0xffffffffu, hm.x, 1);
        float r5 = __shfl_down_sync(0xffffffffu, hm.y, 1);
        if (edgeL) { l2 = eh.x; l1 = eh.y; }
        if (edgeR) { r4 = eh.x; r5 = eh.y; }

        float m01 = fmaxf(hm.x, hm.y);
        float m12 = fmaxf(hm.y, hm.z);
        float m23 = fmaxf(hm.z, hm.w);
        float4 m;                               // m2d(p), raw
        m.x = fmaxf(fmaxf(l2, l1), fmaxf(m01, hm.z));
        m.y = fmaxf(l1, fmaxf(m01, m23));
        m.z = fmaxf(fmaxf(m01, m23), r4);
        m.w = fmaxf(fmaxf(m12, hm.w), fmaxf(r4, r5));

        if (emit) {
            float4 M3 = fmax4(fmax4(fmax4(rp4, rp3), fmax4(rp2, rp1)), m);
            float4 o;
            o.x = (cen2.x == M3.x && cen2.x > THRESH) ? cen2.x : 0.f;
            o.y = (cen2.y == M3.y && cen2.y > THRESH) ? cen2.y : 0.f;
            o.z = (cen2.z == M3.z && cen2.z > THRESH) ? cen2.z : 0.f;
            o.w = (cen2.w == M3.w && cen2.w > THRESH) ? cen2.w : 0.f;
            *(float4*)outp = o;
            outp += PSZ;
        }

        rp4 = rp3; rp3 = rp2; rp2 = rp1; rp1 = m;
        cen2 = cen1; cen1 = cen;
    };

    #pragma unroll 2
    for (int k = 0; k < NP / 3; ++k) {
        const int p = 3 * k;

        issue(p + 3);       // -> bufs (p-3..p-1)%6; their readers ran pre-BAR(k)
        issue(p + 4);
        issue(p + 5);

        cp_wait3();         // planes p..p+2 complete (p+3..p+5 may pend)
        __syncthreads();    // all threads' copies of p..p+2 visible

        plane(vsm + ( p      % NBUF) * BUFSZ, p     >= 4);
        plane(vsm + ((p + 1) % NBUF) * BUFSZ, p + 1 >= 4);
        plane(vsm + ((p + 2) % NBUF) * BUFSZ, p + 2 >= 4);
    }

    cp_wait0();   // drain trailing groups before exit
}

extern "C" void kernel_launch(void* const* d_in, const int* in_sizes, int n_in,
                              void* d_out, int out_size) {
    (void)in_sizes; (void)n_in; (void)out_size;
    const float* in = (const float*)d_in[0];
    float* out = (float*)d_out;

    const int smem_bytes = NBUF * BUFSZ * (int)sizeof(float);   // 98304
    cudaFuncSetAttribute(peak3d_kernel,
                         cudaFuncAttributeMaxDynamicSharedMemorySize, smem_bytes);

    dim3 block(128, 4);                 // 512 threads
    dim3 grid(Hd / TH, Dd / DCH);       // 128 x 2 = 256 blocks (2/SM resident)
    peak3d_kernel<<<grid, block, smem_bytes>>>(in, out);
}